// round 17
// baseline (speedup 1.0000x reference)
#include <cuda_runtime.h>
#include <cuda_fp16.h>
#include <cstdint>

#define N_NODES 100000
#define N_EDGES 1600000
#define DIM 64
#define SCAN_CHUNK 1024
#define NCH 98
#define TILE_R 128
#define ES_CAP (N_EDGES + 3 * N_NODES)
#define SENTINEL ((4u << 28) | (unsigned)N_NODES)

__device__ float  g_t[(size_t)N_NODES * DIM];
__device__ __half g_h16[(size_t)N_NODES * DIM];         // fp16 h (direct MMA A input)
__device__ __half g_x16[(size_t)(N_NODES + 1) * DIM];   // +1 zero row for sentinels
__device__ uint2  g_wfrag[2 * 1024];                    // per-lane B fragments
__device__ float  g_sum[DIM];
__device__ float  g_sq[DIM];
__device__ int    g_deg[N_NODES];                       // zero at entry (agg resets)
__device__ int    g_off[N_NODES];
__device__ int    g_cur[N_NODES];
__device__ unsigned long long g_state[NCH];             // zero at entry (scatter resets)
__device__ __align__(16) unsigned g_es[ES_CAP];         // (attr<<28) | src, 4-padded

__device__ __forceinline__ uint32_t smem_u32(const void* p) {
    uint32_t a;
    asm("{ .reg .u64 t; cvta.to.shared.u64 t, %1; cvt.u32.u64 %0, t; }" : "=r"(a) : "l"(p));
    return a;
}

// ---------------------------------------------------------------------------
// K0: hist — dst histogram (4 edges/thread) + W1/W2 mma B fragments
// ---------------------------------------------------------------------------
__global__ void hist_kernel(const int* __restrict__ ei,
                            const float* __restrict__ W1, const float* __restrict__ W2) {
    int i = blockIdx.x * 256 + threadIdx.x;
    if (i < N_EDGES / 4) {
        int4 d = ((const int4*)(ei + N_EDGES))[i];
        atomicAdd(&g_deg[d.x], 1); atomicAdd(&g_deg[d.y], 1);
        atomicAdd(&g_deg[d.z], 1); atomicAdd(&g_deg[d.w], 1);
    }
    if (i < 2048) {   // B frag: lane g=lane>>2, tid4=lane&3; n=j*8+g; k0=s*16+tid4*2
        int which = i >> 10, r = i & 1023;
        int s = r >> 8, rem = r & 255, j = rem >> 5, lane = rem & 31;
        int g = lane >> 2, tid4 = lane & 3;
        int n = j * 8 + g;
        int k0 = s * 16 + tid4 * 2;
        const float* W = which ? W2 : W1;
        __half2 bx = __floats2half2_rn(__ldg(W + k0 * DIM + n), __ldg(W + (k0 + 1) * DIM + n));
        __half2 by = __floats2half2_rn(__ldg(W + (k0 + 8) * DIM + n), __ldg(W + (k0 + 9) * DIM + n));
        uint2 u;
        u.x = *(unsigned*)&bx; u.y = *(unsigned*)&by;
        g_wfrag[which * 1024 + r] = u;
    }
}

// ---------------------------------------------------------------------------
// K1: single-launch scan over PADDED degrees; writes sentinel pad entries;
// stores padded degree back into g_deg. Blk0 zeroes BN accums.
// ---------------------------------------------------------------------------
__global__ void scan_kernel() {
    __shared__ int warp_sums[32];
    __shared__ int s_tot[128];
    int b = blockIdx.x, idx = b * SCAN_CHUNK + threadIdx.x;
    int d = (idx < N_NODES) ? g_deg[idx] : 0;
    int d4 = (d + 3) & ~3;
    int lane = threadIdx.x & 31, wid = threadIdx.x >> 5;

    int v = d4;
    #pragma unroll
    for (int o = 1; o < 32; o <<= 1) { int t = __shfl_up_sync(~0u, v, o); if (lane >= o) v += t; }
    if (lane == 31) warp_sums[wid] = v;
    __syncthreads();
    if (wid == 0) {
        int s = warp_sums[lane];
        #pragma unroll
        for (int o = 1; o < 32; o <<= 1) { int t = __shfl_up_sync(~0u, s, o); if (lane >= o) s += t; }
        warp_sums[lane] = s;
    }
    __syncthreads();
    int incl = v + (wid > 0 ? warp_sums[wid - 1] : 0);
    int total = warp_sums[31];

    if (threadIdx.x == 0)
        atomicExch(&g_state[b], ((unsigned long long)(unsigned)total << 32) | 1ull);
    if (b == 0 && threadIdx.x < DIM) { g_sum[threadIdx.x] = 0.0f; g_sq[threadIdx.x] = 0.0f; }

    if (threadIdx.x < 128) s_tot[threadIdx.x] = 0;
    __syncthreads();
    if ((int)threadIdx.x < b) {
        unsigned long long st;
        do { st = *(volatile unsigned long long*)&g_state[threadIdx.x]; } while (!(st & 1ull));
        s_tot[threadIdx.x] = (int)(st >> 32);
    }
    __syncthreads();
    if (threadIdx.x < 64) s_tot[threadIdx.x] += s_tot[threadIdx.x + 64];
    __syncthreads();
    if (threadIdx.x < 32) {
        int s = s_tot[threadIdx.x] + s_tot[threadIdx.x + 32];
        #pragma unroll
        for (int o = 16; o > 0; o >>= 1) s += __shfl_down_sync(~0u, s, o);
        if (threadIdx.x == 0) s_tot[0] = s;
    }
    __syncthreads();
    int ex = s_tot[0] + incl - d4;
    if (idx < N_NODES) {
        g_off[idx] = ex;
        g_cur[idx] = ex;
        g_deg[idx] = d4;                           // padded degree for agg
        for (int q = d; q < d4; q++) g_es[ex + q] = SENTINEL;
    }
}

// ---------------------------------------------------------------------------
// K2: scatter packed (attr,src) — 4 edges/thread — PLUS x->fp16 conversion
// (folded here to overlap with ATOMG latency). Blk0 resets g_state.
// ---------------------------------------------------------------------------
#define SCAT_THREADS (1563 * 256)
__global__ void scatter_kernel(const int* __restrict__ ei, const int* __restrict__ ea,
                               const float* __restrict__ x) {
    if (blockIdx.x == 0 && threadIdx.x < NCH) g_state[threadIdx.x] = 0ull;
    int i = blockIdx.x * 256 + threadIdx.x;

    // x -> fp16 (800000 uint4 units, strided)
    for (int u = i; u < N_NODES * DIM / 8; u += SCAT_THREADS) {
        float4 a = __ldg((const float4*)x + 2 * u);
        float4 b = __ldg((const float4*)x + 2 * u + 1);
        __half2 h0 = __floats2half2_rn(a.x, a.y), h1 = __floats2half2_rn(a.z, a.w);
        __half2 h2 = __floats2half2_rn(b.x, b.y), h3 = __floats2half2_rn(b.z, b.w);
        uint4 p;
        p.x = *(unsigned*)&h0; p.y = *(unsigned*)&h1;
        p.z = *(unsigned*)&h2; p.w = *(unsigned*)&h3;
        ((uint4*)g_x16)[u] = p;
    }

    if (i >= N_EDGES / 4) return;
    int4 s = ((const int4*)ei)[i];
    int4 d = ((const int4*)(ei + N_EDGES))[i];
    int4 a = ((const int4*)ea)[i];
    int p0 = atomicAdd(&g_cur[d.x], 1);
    int p1 = atomicAdd(&g_cur[d.y], 1);
    int p2 = atomicAdd(&g_cur[d.z], 1);
    int p3 = atomicAdd(&g_cur[d.w], 1);
    g_es[p0] = (unsigned)s.x | ((unsigned)a.x << 28);
    g_es[p1] = (unsigned)s.y | ((unsigned)a.y << 28);
    g_es[p2] = (unsigned)s.z | ((unsigned)a.z << 28);
    g_es[p3] = (unsigned)s.w | ((unsigned)a.w << 28);
}

// ---------------------------------------------------------------------------
// K3: aggregate — 8 lanes/node; indices via ONE aligned uint4 per 4 edges;
// uniform loop (padded degrees, sentinel edges contribute exactly 0).
// fp32 emb/message math; h stored fp16.
// ---------------------------------------------------------------------------
__global__ void __launch_bounds__(256)
agg_kernel(const float* __restrict__ x, const float* __restrict__ emb,
           const float* __restrict__ eps) {
    __shared__ float s_emb[8 * DIM];     // rows 0-3: emb; rows 4-7: -1e30 (sentinel)
    s_emb[threadIdx.x] = emb[threadIdx.x];
    s_emb[threadIdx.x + 256] = -1e30f;
    __syncthreads();

    int gt = blockIdx.x * 256 + threadIdx.x;
    int n = gt >> 3, lane = gt & 7;
    if (n >= N_NODES) return;

    int off = g_off[n];
    int deg4 = g_deg[n];                 // padded to multiple of 4
    if (lane == 0) g_deg[n] = 0;
    float s = 1.0f + __ldg(eps);

    const float4* xp = (const float4*)(x + (size_t)n * DIM + lane * 8);
    float4 accA = __ldg(xp), accB = __ldg(xp + 1);
    accA.x *= s; accA.y *= s; accA.z *= s; accA.w *= s;
    accB.x *= s; accB.y *= s; accB.z *= s; accB.w *= s;

    const uint4* xb = (const uint4*)g_x16;

    for (int j = 0; j < deg4; j += 4) {
        uint4 pp = __ldg((const uint4*)(g_es + off + j));   // broadcast across 8 lanes
        uint4 r0 = __ldg(xb + (size_t)(pp.x & 0x0FFFFFFFu) * 8 + lane);
        uint4 r1 = __ldg(xb + (size_t)(pp.y & 0x0FFFFFFFu) * 8 + lane);
        uint4 r2 = __ldg(xb + (size_t)(pp.z & 0x0FFFFFFFu) * 8 + lane);
        uint4 r3 = __ldg(xb + (size_t)(pp.w & 0x0FFFFFFFu) * 8 + lane);
        const float4* e0 = (const float4*)(s_emb + (pp.x >> 28) * DIM + lane * 8);
        const float4* e1 = (const float4*)(s_emb + (pp.y >> 28) * DIM + lane * 8);
        const float4* e2 = (const float4*)(s_emb + (pp.z >> 28) * DIM + lane * 8);
        const float4* e3 = (const float4*)(s_emb + (pp.w >> 28) * DIM + lane * 8);
        {
            float2 f0 = __half22float2(*(__half2*)&r0.x), f1 = __half22float2(*(__half2*)&r0.y);
            float2 f2 = __half22float2(*(__half2*)&r0.z), f3 = __half22float2(*(__half2*)&r0.w);
            float4 ea = e0[0], eb = e0[1];
            accA.x += fmaxf(f0.x + ea.x, 0.f); accA.y += fmaxf(f0.y + ea.y, 0.f);
            accA.z += fmaxf(f1.x + ea.z, 0.f); accA.w += fmaxf(f1.y + ea.w, 0.f);
            accB.x += fmaxf(f2.x + eb.x, 0.f); accB.y += fmaxf(f2.y + eb.y, 0.f);
            accB.z += fmaxf(f3.x + eb.z, 0.f); accB.w += fmaxf(f3.y + eb.w, 0.f);
        }
        {
            float2 f0 = __half22float2(*(__half2*)&r1.x), f1 = __half22float2(*(__half2*)&r1.y);
            float2 f2 = __half22float2(*(__half2*)&r1.z), f3 = __half22float2(*(__half2*)&r1.w);
            float4 ea = e1[0], eb = e1[1];
            accA.x += fmaxf(f0.x + ea.x, 0.f); accA.y += fmaxf(f0.y + ea.y, 0.f);
            accA.z += fmaxf(f1.x + ea.z, 0.f); accA.w += fmaxf(f1.y + ea.w, 0.f);
            accB.x += fmaxf(f2.x + eb.x, 0.f); accB.y += fmaxf(f2.y + eb.y, 0.f);
            accB.z += fmaxf(f3.x + eb.z, 0.f); accB.w += fmaxf(f3.y + eb.w, 0.f);
        }
        {
            float2 f0 = __half22float2(*(__half2*)&r2.x), f1 = __half22float2(*(__half2*)&r2.y);
            float2 f2 = __half22float2(*(__half2*)&r2.z), f3 = __half22float2(*(__half2*)&r2.w);
            float4 ea = e2[0], eb = e2[1];
            accA.x += fmaxf(f0.x + ea.x, 0.f); accA.y += fmaxf(f0.y + ea.y, 0.f);
            accA.z += fmaxf(f1.x + ea.z, 0.f); accA.w += fmaxf(f1.y + ea.w, 0.f);
            accB.x += fmaxf(f2.x + eb.x, 0.f); accB.y += fmaxf(f2.y + eb.y, 0.f);
            accB.z += fmaxf(f3.x + eb.z, 0.f); accB.w += fmaxf(f3.y + eb.w, 0.f);
        }
        {
            float2 f0 = __half22float2(*(__half2*)&r3.x), f1 = __half22float2(*(__half2*)&r3.y);
            float2 f2 = __half22float2(*(__half2*)&r3.z), f3 = __half22float2(*(__half2*)&r3.w);
            float4 ea = e3[0], eb = e3[1];
            accA.x += fmaxf(f0.x + ea.x, 0.f); accA.y += fmaxf(f0.y + ea.y, 0.f);
            accA.z += fmaxf(f1.x + ea.z, 0.f); accA.w += fmaxf(f1.y + ea.w, 0.f);
            accB.x += fmaxf(f2.x + eb.x, 0.f); accB.y += fmaxf(f2.y + eb.y, 0.f);
            accB.z += fmaxf(f3.x + eb.z, 0.f); accB.w += fmaxf(f3.y + eb.w, 0.f);
        }
    }

    __half2 h0 = __floats2half2_rn(accA.x, accA.y), h1 = __floats2half2_rn(accA.z, accA.w);
    __half2 h2 = __floats2half2_rn(accB.x, accB.y), h3 = __floats2half2_rn(accB.z, accB.w);
    uint4 pk;
    pk.x = *(unsigned*)&h0; pk.y = *(unsigned*)&h1;
    pk.z = *(unsigned*)&h2; pk.w = *(unsigned*)&h3;
    *(uint4*)(g_h16 + (size_t)n * DIM + lane * 8) = pk;
}

// ---------------------------------------------------------------------------
// K4/K5: HMMA GEMM (mma.sync.m16n8k16), 256 threads, 128-row tile.
// MODE 0: A = g_h16 (raw fp16 copy). MODE 1: A = relu(g_t*aff) -> fp16.
// ---------------------------------------------------------------------------
#define A_STRIDE 72

template <int MODE>
__global__ void __launch_bounds__(256)
gemm_mma(const float* __restrict__ bias, const float* __restrict__ gamma,
         const float* __restrict__ beta, float* __restrict__ out_ext) {
    __shared__ __align__(16) __half sA[128 * A_STRIDE];
    __shared__ uint2 sFrag[1024];
    __shared__ float sBias[64], sAff[128], sSum[64], sSq[64];

    int t = threadIdx.x;
    int r0 = blockIdx.x * TILE_R;
    float* out = (MODE == 0) ? g_t : out_ext;

    if (t < 64) {
        sBias[t] = __ldg(bias + t);
        sSum[t] = 0.0f; sSq[t] = 0.0f;
        if (MODE == 1) {
            const float inv = 1.0f / (float)N_NODES;
            float mu = g_sum[t] * inv, var = g_sq[t] * inv - mu * mu;
            float a = gamma[t] * rsqrtf(var + 1e-5f);
            sAff[t] = a; sAff[64 + t] = fmaf(-mu, a, beta[t]);
        }
    }
    {
        const uint2* src = g_wfrag + (MODE == 0 ? 0 : 1024);
        #pragma unroll
        for (int q = 0; q < 4; q++) sFrag[t + 256 * q] = __ldg(src + t + 256 * q);
    }
    if (MODE == 1) __syncthreads();

    if (MODE == 0) {
        int row_l = t >> 1, half = t & 1;
        int row = r0 + row_l;
        bool valid = row < N_NODES;
        const uint4* rp = (const uint4*)(g_h16 + (size_t)row * DIM + half * 32);
        uint4* dst = (uint4*)(sA + row_l * A_STRIDE + half * 32);
        #pragma unroll
        for (int q = 0; q < 4; q++)
            dst[q] = valid ? __ldg(rp + q) : make_uint4(0, 0, 0, 0);
    } else {
        int row_l = t >> 1, half = t & 1;
        int row = r0 + row_l;
        bool valid = row < N_NODES;
        const float4* rp = (const float4*)(g_t + (size_t)row * DIM + half * 32);
        __half* dst = sA + row_l * A_STRIDE + half * 32;
        #pragma unroll
        for (int q = 0; q < 8; q++) {
            float4 v = valid ? __ldg(rp + q) : make_float4(0.f, 0.f, 0.f, 0.f);
            int k0 = half * 32 + q * 4;
            v.x = fmaxf(fmaf(v.x, sAff[k0+0], sAff[64+k0+0]), 0.f);
            v.y = fmaxf(fmaf(v.y, sAff[k0+1], sAff[64+k0+1]), 0.f);
            v.z = fmaxf(fmaf(v.z, sAff[k0+2], sAff[64+k0+2]), 0.f);
            v.w = fmaxf(fmaf(v.w, sAff[k0+3], sAff[64+k0+3]), 0.f);
            __half2 h0 = __floats2half2_rn(v.x, v.y), h1 = __floats2half2_rn(v.z, v.w);
            uint2 pk;
            pk.x = *(unsigned*)&h0; pk.y = *(unsigned*)&h1;
            *(uint2*)(dst + q * 4) = pk;
        }
    }
    __syncthreads();

    int wid = t >> 5, lane = t & 31;
    int m0 = wid * 16;
    int g = lane >> 2, tid4 = lane & 3;

    float acc[8][4];
    #pragma unroll
    for (int j = 0; j < 8; j++)
        #pragma unroll
        for (int c = 0; c < 4; c++) acc[j][c] = 0.0f;

    #pragma unroll
    for (int s = 0; s < 4; s++) {
        uint32_t a0, a1, a2, a3;
        uint32_t addr = smem_u32(sA + (m0 + (lane & 15)) * A_STRIDE + s * 16 + (lane >> 4) * 8);
        asm volatile("ldmatrix.sync.aligned.m8n8.x4.shared.b16 {%0,%1,%2,%3}, [%4];"
                     : "=r"(a0), "=r"(a1), "=r"(a2), "=r"(a3) : "r"(addr));
        #pragma unroll
        for (int j = 0; j < 8; j++) {
            uint2 b = sFrag[(s * 8 + j) * 32 + lane];
            asm volatile(
                "mma.sync.aligned.m16n8k16.row.col.f32.f16.f16.f32 "
                "{%0,%1,%2,%3}, {%4,%5,%6,%7}, {%8,%9}, {%0,%1,%2,%3};"
                : "+f"(acc[j][0]), "+f"(acc[j][1]), "+f"(acc[j][2]), "+f"(acc[j][3])
                : "r"(a0), "r"(a1), "r"(a2), "r"(a3), "r"(b.x), "r"(b.y));
        }
    }

    int r1 = r0 + m0 + g, r2 = r1 + 8;
    bool v1 = r1 < N_NODES, v2 = r2 < N_NODES;
    #pragma unroll
    for (int j = 0; j < 8; j++) {
        int n = j * 8 + tid4 * 2;
        float b0 = sBias[n], b1 = sBias[n + 1];
        float v00 = acc[j][0] + b0, v01 = acc[j][1] + b1;
        float v10 = acc[j][2] + b0, v11 = acc[j][3] + b1;
        if (v1) *(float2*)(out + (size_t)r1 * DIM + n) = make_float2(v00, v01);
        if (v2) *(float2*)(out + (size_t)r2 * DIM + n) = make_float2(v10, v11);
        if (MODE == 0) {
            float su0 = (v1 ? v00 : 0.f) + (v2 ? v10 : 0.f);
            float su1 = (v1 ? v01 : 0.f) + (v2 ? v11 : 0.f);
            float sq0 = (v1 ? v00 * v00 : 0.f) + (v2 ? v10 * v10 : 0.f);
            float sq1 = (v1 ? v01 * v01 : 0.f) + (v2 ? v11 * v11 : 0.f);
            #pragma unroll
            for (int o = 16; o >= 4; o >>= 1) {
                su0 += __shfl_down_sync(~0u, su0, o);
                su1 += __shfl_down_sync(~0u, su1, o);
                sq0 += __shfl_down_sync(~0u, sq0, o);
                sq1 += __shfl_down_sync(~0u, sq1, o);
            }
            if (lane < 4) {
                int nn = j * 8 + lane * 2;
                atomicAdd(&sSum[nn], su0);
                atomicAdd(&sSum[nn + 1], su1);
                atomicAdd(&sSq[nn], sq0);
                atomicAdd(&sSq[nn + 1], sq1);
            }
        }
    }
    if (MODE == 0) {
        __syncthreads();
        if (t < 64) { atomicAdd(&g_sum[t], sSum[t]); atomicAdd(&g_sq[t], sSq[t]); }
    }
}

// ---------------------------------------------------------------------------
extern "C" void kernel_launch(void* const* d_in, const int* in_sizes, int n_in,
                              void* d_out, int out_size) {
    const float* x     = (const float*)d_in[0];
    const float* emb   = (const float*)d_in[1];
    const float* eps   = (const float*)d_in[2];
    const float* W1    = (const float*)d_in[3];
    const float* b1    = (const float*)d_in[4];
    const float* gamma = (const float*)d_in[5];
    const float* beta  = (const float*)d_in[6];
    const float* W2    = (const float*)d_in[7];
    const float* b2    = (const float*)d_in[8];
    const int*   ei    = (const int*)d_in[9];
    const int*   ea    = (const int*)d_in[10];
    float*       out   = (float*)d_out;

    hist_kernel<<<(N_EDGES / 4 + 255) / 256, 256>>>(ei, W1, W2);        // 1563
    scan_kernel<<<NCH, SCAN_CHUNK>>>();
    scatter_kernel<<<(N_EDGES / 4 + 255) / 256, 256>>>(ei, ea, x);      // 1563
    agg_kernel<<<(N_NODES * 8 + 255) / 256, 256>>>(x, emb, eps);        // 3125
    const int gblocks = (N_NODES + TILE_R - 1) / TILE_R;                // 782
    gemm_mma<0><<<gblocks, 256>>>(b1, nullptr, nullptr, nullptr);
    gemm_mma<1><<<gblocks, 256>>>(b2, gamma, beta, out);
}